// round 15
// baseline (speedup 1.0000x reference)
#include <cuda_runtime.h>
#include <cuda_fp16.h>
#include <math.h>
#include <stdint.h>

// Problem dims
#define SS 50
#define LL 1024
#define DD 768
#define DD4 192
#define SP 64
#define QKN 384

// ---------------- static scratch (alloc-free rule) ----------------
__device__ __half g_xh[(size_t)SS * LL * DD];
__device__ __half g_lnh[(size_t)SS * LL * DD];
__device__ __half g_xtph[(size_t)LL * SP * DD];
__device__ __half g_qkh[(size_t)LL * SP * QKN];
__device__ __half g_avh[(size_t)SS * LL * DD];
__device__ __half g_scoresh[(size_t)SS * LL * LL];
__device__ float  g_rsum[(size_t)LL * SP];
__device__ __half g_wh[119000000];

// =============== helpers =====================
__device__ __forceinline__ uint32_t smem_u32(const void* p) {
    uint32_t a;
    asm("{ .reg .u64 t; cvta.to.shared.u64 t, %1; cvt.u32.u64 %0, t; }" : "=r"(a) : "l"(p));
    return a;
}
__device__ __forceinline__ void mma_f16(float* d, const uint32_t* a, const uint32_t* b) {
    asm volatile(
        "mma.sync.aligned.m16n8k16.row.col.f32.f16.f16.f32 "
        "{%0,%1,%2,%3}, {%4,%5,%6,%7}, {%8,%9}, {%0,%1,%2,%3};\n"
        : "+f"(d[0]), "+f"(d[1]), "+f"(d[2]), "+f"(d[3])
        : "r"(a[0]), "r"(a[1]), "r"(a[2]), "r"(a[3]),
          "r"(b[0]), "r"(b[1]));
}
__device__ __forceinline__ void ldsm_x4(uint32_t& r0, uint32_t& r1, uint32_t& r2, uint32_t& r3,
                                        uint32_t addr) {
    asm volatile("ldmatrix.sync.aligned.m8n8.x4.shared.b16 {%0,%1,%2,%3}, [%4];"
                 : "=r"(r0), "=r"(r1), "=r"(r2), "=r"(r3) : "r"(addr));
}
__device__ __forceinline__ void ldsm_x4_t(uint32_t& r0, uint32_t& r1, uint32_t& r2, uint32_t& r3,
                                          uint32_t addr) {
    asm volatile("ldmatrix.sync.aligned.m8n8.x4.trans.shared.b16 {%0,%1,%2,%3}, [%4];"
                 : "=r"(r0), "=r"(r1), "=r"(r2), "=r"(r3) : "r"(addr));
}
__device__ __forceinline__ void cp_async16(uint32_t smem_addr, const void* gptr, uint32_t src_bytes) {
    asm volatile("cp.async.ca.shared.global [%0], [%1], 16, %2;"
                 :: "r"(smem_addr), "l"(gptr), "r"(src_bytes));
}
#define CP_COMMIT() asm volatile("cp.async.commit_group;" ::: "memory")
#define CP_WAIT2()  asm volatile("cp.async.wait_group 2;" ::: "memory")

// =================================================================
// cp.async-pipelined FP16 GEMM (mma.sync m16n8k16, ldmatrix frags)
// NT: C = A @ B^T (B [N,K]); NN: C = A @ B (B [K,N], ldmatrix.trans)
// BN in {256, 192, 128}. BM=128 always.
//   BN=256: warps 2m x 4n, warp tile 64x64
//   BN=192: warps 2m x 4n, warp tile 64x48
//   BN=128: warps 4m x 2n, warp tile 32x64
// MODE: 0 plain | 1 +bias | 2 +bias+relu
//     | 3 exp(escale*v), mask col>=nvalid to 0, atomicAdd row sums into rsum_out
//     | 4 v / rowsum[row]
// fp16 out, fp32 accum.
// =================================================================
#define BMt 128
#define RS 20
#define AWORDS (BMt * RS)
#define NSTAGE 4

template<bool TRANSB, int MODE, int BN>
__global__ __launch_bounds__(256, (BN == 128) ? 2 : 1)
void mma_gemm_kernel(const __half* __restrict__ Ab, const __half* __restrict__ Bb,
                     const float* __restrict__ biasb, __half* __restrict__ Cb,
                     int M, int N, int K, int lda, int ldb, int ldc,
                     long sA, long sB, long sBias, long sC,
                     float escale, const float* __restrict__ rowscale, long sRS,
                     float* __restrict__ rsum_out, int nvalid)
{
    constexpr bool BIAS = (MODE == 1 || MODE == 2);
    constexpr bool RELU = (MODE == 2);
    constexpr int BWRD = (BN == 256) ? 5120 : (BN == 192) ? 3840 : 2560;
    constexpr int STGW_L = AWORDS + BWRD;
    constexpr int NAM = (BN == 128) ? 2 : 4;
    constexpr int NBN = (BN == 192) ? 6 : 8;
    constexpr int PBN = NBN / 2;
    constexpr int BRS = (BN == 256) ? 132 : (BN == 192) ? 100 : 68;  // NN B row stride
    constexpr int WN  = (BN == 192) ? 48 : 64;
    constexpr int CH  = BN / 8;        // NN chunks per k-row
    constexpr int NIT = BN / 64;       // staging iters for B

    extern __shared__ __align__(16) uint32_t sm[];
    const uint32_t smb = smem_u32(sm);

    const int b = blockIdx.z;
    const __half* A = Ab + (long)b * sA;
    const __half* B = Bb + (long)b * sB;
    __half* C = Cb + (long)b * sC;

    const int brow = blockIdx.y * BMt;
    const int bcol = blockIdx.x * BN;
    const int tid = threadIdx.x;
    const int wid = tid >> 5;
    const int lane = tid & 31;
    const int g = lane >> 2;
    const int c = lane & 3;
    const int warp_m = (BN == 128) ? (wid & 3) * 32 : (wid & 1) * 64;
    const int warp_n = (BN == 128) ? (wid >> 2) * 64 : (wid >> 1) * WN;

    const int a_row  = (lane & 7) + ((lane >> 3) & 1) * 8;
    const int a_koff = ((lane >> 4) & 1) * 8;
    const int bt_row  = (lane & 7) + ((lane >> 4) & 1) * 8;
    const int bt_koff = ((lane >> 3) & 1) * 8;
    const int bn_k = (lane & 7) + ((lane >> 3) & 1) * 8;
    const int bn_n = ((lane >> 4) & 1) * 8;

    const int nkt = K >> 5;

    float acc[NAM][NBN][4];
    #pragma unroll
    for (int i = 0; i < NAM; i++)
        #pragma unroll
        for (int j = 0; j < NBN; j++)
            #pragma unroll
            for (int r = 0; r < 4; r++)
                acc[i][j][r] = 0.0f;

    auto issue_stage = [&](int kt) {
        if (kt < nkt) {
            int k0 = kt << 5;
            uint32_t sbase = smb + ((kt & (NSTAGE - 1)) * STGW_L) * 4;
            #pragma unroll
            for (int i = 0; i < 2; i++) {
                int idx = i * 256 + tid;
                int row = idx >> 2, q = idx & 3;
                int gr = brow + row;
                const __half* gp = A + (long)gr * lda + k0 + q * 8;
                uint32_t dst = sbase + (row * RS + q * 4) * 4;
                cp_async16(dst, gp, (gr < M) ? 16u : 0u);
            }
            if (TRANSB) {
                #pragma unroll
                for (int i = 0; i < NIT; i++) {
                    int idx = i * 256 + tid;
                    int row = idx >> 2, q = idx & 3;
                    int gn = bcol + row;
                    const __half* gp = B + (long)gn * ldb + k0 + q * 8;
                    uint32_t dst = sbase + (AWORDS + row * RS + q * 4) * 4;
                    cp_async16(dst, gp, (gn < N) ? 16u : 0u);
                }
            } else {
                #pragma unroll
                for (int i = 0; i < NIT; i++) {
                    int idx = i * 256 + tid;
                    int kk = idx / CH, ch = idx % CH;
                    int gn = bcol + ch * 8;
                    const __half* gp = B + (long)(k0 + kk) * ldb + gn;
                    uint32_t dst = sbase + (AWORDS + kk * BRS + ch * 4) * 4;
                    cp_async16(dst, gp, (gn < N) ? 16u : 0u);
                }
            }
        }
        CP_COMMIT();
    };

    issue_stage(0);
    issue_stage(1);
    issue_stage(2);

    for (int kt = 0; kt < nkt; kt++) {
        CP_WAIT2();
        __syncthreads();
        issue_stage(kt + 3);

        uint32_t As = smb + ((kt & (NSTAGE - 1)) * STGW_L) * 4;
        uint32_t Bs = As + AWORDS * 4;

        #pragma unroll
        for (int ks = 0; ks < 2; ks++) {
            int kh = ks * 16;
            uint32_t af[NAM][4], bf[NBN][2];
            #pragma unroll
            for (int am = 0; am < NAM; am++) {
                uint32_t addr = As + ((warp_m + am * 16 + a_row) * RS) * 4
                                   + (kh + a_koff) * 2;
                ldsm_x4(af[am][0], af[am][1], af[am][2], af[am][3], addr);
            }
            #pragma unroll
            for (int p = 0; p < PBN; p++) {
                if (TRANSB) {
                    uint32_t addr = Bs + ((warp_n + p * 16 + bt_row) * RS) * 4
                                       + (kh + bt_koff) * 2;
                    ldsm_x4(bf[2 * p][0], bf[2 * p][1], bf[2 * p + 1][0], bf[2 * p + 1][1], addr);
                } else {
                    uint32_t addr = Bs + ((kh + bn_k) * BRS) * 4
                                       + (warp_n + p * 16 + bn_n) * 2;
                    ldsm_x4_t(bf[2 * p][0], bf[2 * p][1], bf[2 * p + 1][0], bf[2 * p + 1][1], addr);
                }
            }
            #pragma unroll
            for (int am = 0; am < NAM; am++)
                #pragma unroll
                for (int bn = 0; bn < NBN; bn++)
                    mma_f16(acc[am][bn], af[am], bf[bn]);
        }
    }

    // ---- epilogue (fp16 out) ----
    #pragma unroll
    for (int am = 0; am < NAM; am++) {
        int row0 = brow + warp_m + am * 16 + g;
        float rs0 = 1.0f, rs1 = 1.0f;
        if (MODE == 4) {
            rs0 = (row0 < M)     ? 1.0f / rowscale[(long)b * sRS + row0]     : 0.0f;
            rs1 = (row0 + 8 < M) ? 1.0f / rowscale[(long)b * sRS + row0 + 8] : 0.0f;
        }
        float rowacc0 = 0.0f, rowacc1 = 0.0f;
        #pragma unroll
        for (int bn = 0; bn < NBN; bn++) {
            int col = bcol + warp_n + bn * 8 + c * 2;
            if (col >= N) continue;
            float v0 = acc[am][bn][0], v1 = acc[am][bn][1];
            float v2 = acc[am][bn][2], v3 = acc[am][bn][3];
            if (BIAS) {
                float b0 = biasb[(long)b * sBias + col];
                float b1 = biasb[(long)b * sBias + col + 1];
                v0 += b0; v1 += b1; v2 += b0; v3 += b1;
            }
            if (RELU) {
                v0 = fmaxf(v0, 0.f); v1 = fmaxf(v1, 0.f);
                v2 = fmaxf(v2, 0.f); v3 = fmaxf(v3, 0.f);
            }
            if (MODE == 3) {
                v0 = (col     < nvalid) ? __expf(v0 * escale) : 0.0f;
                v1 = (col + 1 < nvalid) ? __expf(v1 * escale) : 0.0f;
                v2 = (col     < nvalid) ? __expf(v2 * escale) : 0.0f;
                v3 = (col + 1 < nvalid) ? __expf(v3 * escale) : 0.0f;
                rowacc0 += v0 + v1;
                rowacc1 += v2 + v3;
            }
            if (MODE == 4) {
                v0 *= rs0; v1 *= rs0; v2 *= rs1; v3 *= rs1;
            }
            __half2 h01 = __floats2half2_rn(v0, v1);
            __half2 h23 = __floats2half2_rn(v2, v3);
            if (row0 < M)     *(__half2*)&C[(long)row0 * ldc + col]       = h01;
            if (row0 + 8 < M) *(__half2*)&C[(long)(row0 + 8) * ldc + col] = h23;
        }
        if (MODE == 3) {
            // reduce across the 4 c-lanes sharing this row, then 1 atomic per warp
            rowacc0 += __shfl_xor_sync(0xffffffffu, rowacc0, 1);
            rowacc0 += __shfl_xor_sync(0xffffffffu, rowacc0, 2);
            rowacc1 += __shfl_xor_sync(0xffffffffu, rowacc1, 1);
            rowacc1 += __shfl_xor_sync(0xffffffffu, rowacc1, 2);
            if (c == 0) {
                if (row0 < M)     atomicAdd(&rsum_out[(long)b * sRS + row0],     rowacc0);
                if (row0 + 8 < M) atomicAdd(&rsum_out[(long)b * sRS + row0 + 8], rowacc1);
            }
        }
    }
}

// ---------------- float -> half elementwise ----------------
__global__ __launch_bounds__(256)
void f2h_kernel(const float* __restrict__ in, __half* __restrict__ out, long n4)
{
    long i = (long)blockIdx.x * 256 + threadIdx.x;
    if (i >= n4) return;
    float4 v = ((const float4*)in)[i];
    ((__half2*)out)[i * 2]     = __floats2half2_rn(v.x, v.y);
    ((__half2*)out)[i * 2 + 1] = __floats2half2_rn(v.z, v.w);
}

// ------- concat Wq||Wk -> half [batch, D, QKN] --------
__global__ __launch_bounds__(256)
void concat_qk_kernel(const float* __restrict__ Wq, const float* __restrict__ Wk,
                      __half* __restrict__ out, long total)
{
    long i = (long)blockIdx.x * 256 + threadIdx.x;
    if (i >= total) return;
    long j = i % QKN;
    long bd = i / QKN;
    float v = (j < DD4) ? Wq[bd * DD4 + j] : Wk[bd * DD4 + (j - DD4)];
    out[i] = __float2half_rn(v);
}

// ---------------- zero floats ----------------
__global__ __launch_bounds__(256)
void zerof_kernel(float* __restrict__ p, long n)
{
    long i = (long)blockIdx.x * 256 + threadIdx.x;
    if (i < n) p[i] = 0.0f;
}

// ------ warp-per-row fused residual + LayerNorm (fp16 stream, fp32 math) ------
__global__ __launch_bounds__(256)
void ln_kernel(const __half* __restrict__ resid, const __half* __restrict__ h,
               const float* __restrict__ gam, const float* __restrict__ bet,
               __half* __restrict__ outh, float* __restrict__ outf, int J,
               long ri, long rj, long hi, long hj, long oi, long oj, long gstride,
               long nrows)
{
    int wid = threadIdx.x >> 5, lane = threadIdx.x & 31;
    long row = (long)blockIdx.x * 8 + wid;
    if (row >= nrows) return;
    long i = row / J, j = row % J;
    const __half2* r2 = (const __half2*)(resid + (i * ri + j * rj) * DD);
    const __half2* h2 = (const __half2*)(h     + (i * hi + j * hj) * DD);
    long orow = i * oi + j * oj;
    const float2* gp = (const float2*)(gam + i * gstride);
    const float2* bp = (const float2*)(bet + i * gstride);

    float2 v[12];
    float s = 0.0f, s2 = 0.0f;
    #pragma unroll
    for (int k = 0; k < 12; k++) {
        int d = lane + k * 32;
        float2 a = __half22float2(r2[d]);
        float2 b = __half22float2(h2[d]);
        float2 val = make_float2(a.x + b.x, a.y + b.y);
        v[k] = val;
        s += val.x + val.y;
        s2 += val.x * val.x + val.y * val.y;
    }
    #pragma unroll
    for (int o = 16; o > 0; o >>= 1) {
        s  += __shfl_xor_sync(0xffffffffu, s, o);
        s2 += __shfl_xor_sync(0xffffffffu, s2, o);
    }
    float mean = s * (1.0f / DD);
    float var  = s2 * (1.0f / DD) - mean * mean;
    float inv  = rsqrtf(var + 1e-5f);

    #pragma unroll
    for (int k = 0; k < 12; k++) {
        int d = lane + k * 32;
        float2 gg = gp[d], bb = bp[d];
        float o0 = (v[k].x - mean) * inv * gg.x + bb.x;
        float o1 = (v[k].y - mean) * inv * gg.y + bb.y;
        if (outh) ((__half2*)(outh + orow * DD))[d] = __floats2half2_rn(o0, o1);
        if (outf) ((float2*)(outf + orow * DD))[d] = make_float2(o0, o1);
    }
}

// ---------------- zero pad rows of xtph [LL, SP, DD] ----------------
__global__ __launch_bounds__(256)
void zero_pad_kernel(__half* __restrict__ xth)
{
    long idx = (long)blockIdx.x * 256 + threadIdx.x;
    const long per_l = (long)(SP - SS) * DD;
    const long total = (long)LL * per_l;
    if (idx >= total) return;
    long l = idx / per_l;
    long off = idx % per_l;
    xth[((long)l * SP + SS) * DD + off] = __float2half_rn(0.0f);
}

// ---------------- launch plumbing ----------------
static inline int cdiv(int a, int b) { return (a + b - 1) / b; }

template<bool TRANSB, int MODE, int BN>
static void launch_gemm(const __half* A, const __half* B, const float* bias, __half* C,
                        int M, int N, int K, int lda, int ldb, int ldc, int batch,
                        long sA, long sB, long sBias, long sC,
                        float escale = 0.0f, const float* rowscale = nullptr, long sRS = 0,
                        float* rsum_out = nullptr, int nvalid = 1 << 30)
{
    const int BWRD = (BN == 256) ? 5120 : (BN == 192) ? 3840 : 2560;
    const int smem = (AWORDS + BWRD) * NSTAGE * 4;
    dim3 grid(cdiv(N, BN), cdiv(M, BMt), batch);
    cudaFuncSetAttribute(mma_gemm_kernel<TRANSB, MODE, BN>,
                         cudaFuncAttributeMaxDynamicSharedMemorySize, smem);
    mma_gemm_kernel<TRANSB, MODE, BN><<<grid, 256, smem>>>(
        A, B, bias, C, M, N, K, lda, ldb, ldc, sA, sB, sBias, sC,
        escale, rowscale, sRS, rsum_out, nvalid);
}

extern "C" void kernel_launch(void* const* d_in, const int* in_sizes, int n_in,
                              void* d_out, int out_size)
{
    (void)in_sizes; (void)n_in; (void)out_size;

    const float* x        = (const float*)d_in[0];
    const float* pre_Wq   = (const float*)d_in[1];
    const float* pre_Wk   = (const float*)d_in[2];
    const float* pre_Wv   = (const float*)d_in[3];
    const float* ln1_g    = (const float*)d_in[4];
    const float* ln1_b    = (const float*)d_in[5];
    const float* pre_W1   = (const float*)d_in[6];
    const float* pre_b1   = (const float*)d_in[7];
    const float* pre_W2   = (const float*)d_in[8];
    const float* pre_b2   = (const float*)d_in[9];
    const float* ln4p_g   = (const float*)d_in[10];
    const float* ln4p_b   = (const float*)d_in[11];
    const float* cross_Wq = (const float*)d_in[12];
    const float* cross_Wk = (const float*)d_in[13];
    const float* cross_Wv = (const float*)d_in[14];
    const float* ln2_g    = (const float*)d_in[15];
    const float* ln2_b    = (const float*)d_in[16];
    const float* post_Wq  = (const float*)d_in[17];
    const float* post_Wk  = (const float*)d_in[18];
    const float* post_Wv  = (const float*)d_in[19];
    const float* ln3_g    = (const float*)d_in[20];
    const float* ln3_b    = (const float*)d_in[21];
    const float* post_W1  = (const float*)d_in[22];
    const float* post_b1  = (const float*)d_in[23];
    const float* post_W2  = (const float*)d_in[24];
    const float* post_b2  = (const float*)d_in[25];
    const float* ln4_g    = (const float*)d_in[26];
    const float* ln4_b    = (const float*)d_in[27];
    float* out = (float*)d_out;

    __half *xh, *lnh, *xtph, *qkh, *avh, *scoresh, *wh;
    float* rsum;
    cudaGetSymbolAddress((void**)&xh, g_xh);
    cudaGetSymbolAddress((void**)&lnh, g_lnh);
    cudaGetSymbolAddress((void**)&xtph, g_xtph);
    cudaGetSymbolAddress((void**)&qkh, g_qkh);
    cudaGetSymbolAddress((void**)&avh, g_avh);
    cudaGetSymbolAddress((void**)&scoresh, g_scoresh);
    cudaGetSymbolAddress((void**)&rsum, g_rsum);
    cudaGetSymbolAddress((void**)&wh, g_wh);

    const long SZ_QKW = (long)SS * DD * QKN;
    const long SZ_VW  = (long)SS * DD * DD;
    const long SZ_W1  = (long)SS * DD * DD4;
    __half* qkPreH   = wh;
    __half* qkPostH  = qkPreH  + SZ_QKW;
    __half* qkCrossH = qkPostH + SZ_QKW;
    __half* WvPreH   = qkCrossH + (long)DD * QKN;
    __half* WvPostH  = WvPreH  + SZ_VW;
    __half* WvCrossH = WvPostH + SZ_VW;
    __half* W1PreH   = WvCrossH + (long)DD * DD;
    __half* W1PostH  = W1PreH  + SZ_W1;
    __half* W2PreH   = W1PostH + SZ_W1;
    __half* W2PostH  = W2PreH  + SZ_W1;

    const float scale = 1.0f / sqrtf((float)DD4);
    const long LD = (long)LL * DD;

    // ---------------- weight prep: pure streaming f2h / concat ----------
    concat_qk_kernel<<<cdiv((int)SZ_QKW, 256), 256>>>(pre_Wq, pre_Wk, qkPreH, SZ_QKW);
    concat_qk_kernel<<<cdiv((int)SZ_QKW, 256), 256>>>(post_Wq, post_Wk, qkPostH, SZ_QKW);
    concat_qk_kernel<<<cdiv((int)(DD * QKN), 256), 256>>>(cross_Wq, cross_Wk, qkCrossH, (long)DD * QKN);
    f2h_kernel<<<cdiv((int)(SZ_VW / 4), 256), 256>>>(pre_Wv,  WvPreH,  SZ_VW / 4);
    f2h_kernel<<<cdiv((int)(SZ_VW / 4), 256), 256>>>(post_Wv, WvPostH, SZ_VW / 4);
    f2h_kernel<<<cdiv((int)((long)DD * DD / 4), 256), 256>>>(cross_Wv, WvCrossH, (long)DD * DD / 4);
    f2h_kernel<<<cdiv((int)(SZ_W1 / 4), 256), 256>>>(pre_W1,  W1PreH,  SZ_W1 / 4);
    f2h_kernel<<<cdiv((int)(SZ_W1 / 4), 256), 256>>>(post_W1, W1PostH, SZ_W1 / 4);
    f2h_kernel<<<cdiv((int)(SZ_W1 / 4), 256), 256>>>(pre_W2,  W2PreH,  SZ_W1 / 4);
    f2h_kernel<<<cdiv((int)(SZ_W1 / 4), 256), 256>>>(post_W2, W2PostH, SZ_W1 / 4);
    f2h_kernel<<<cdiv((int)(SS * LD / 4), 256), 256>>>(x, xh, SS * LD / 4);

    // ================= pre_self_step attention =================
    launch_gemm<false, 0, 128>(xh, qkPreH, nullptr, qkh, LL, QKN, DD, DD, QKN, QKN, SS,
                               LD, (long)DD * QKN, 0, (long)LL * QKN);
    zerof_kernel<<<cdiv(SS * LL, 256), 256>>>(rsum, (long)SS * LL);
    launch_gemm<true, 3, 256>(qkh, qkh + DD4, nullptr, scoresh, LL, LL, DD4, QKN, QKN, LL, SS,
                              (long)LL * QKN, (long)LL * QKN, 0, (long)LL * LL,
                              scale, nullptr, LL, rsum, LL);
    launch_gemm<false, 4, 256>(scoresh, xh, nullptr, avh, LL, DD, LL, LL, DD, DD, SS,
                               (long)LL * LL, LD, 0, LD, 0.0f, rsum, LL);
    launch_gemm<false, 0, 256>(avh, WvPreH, nullptr, scoresh, LL, DD, DD, DD, DD, DD, SS,
                               LD, (long)DD * DD, 0, LD);
    ln_kernel<<<SS * LL / 8, 256>>>(xh, scoresh, ln1_g, ln1_b, lnh, nullptr, LL,
                                    LL, 1, LL, 1, LL, 1, DD, (long)SS * LL);

    // ================= pre_mlp =================
    launch_gemm<false, 2, 192>(lnh, W1PreH, pre_b1, qkh, LL, DD4, DD, DD, DD4, DD4, SS,
                               LD, (long)DD * DD4, DD4, (long)LL * DD4);
    launch_gemm<false, 1, 256>(qkh, W2PreH, pre_b2, scoresh, LL, DD, DD4, DD4, DD, DD, SS,
                               (long)LL * DD4, (long)DD4 * DD, DD, LD);
    ln_kernel<<<SS * LL / 8, 256>>>(lnh, scoresh, ln4p_g, ln4p_b, xtph, nullptr, LL,
                                    LL, 1, LL, 1, 1, SP, DD, (long)SS * LL);
    zero_pad_kernel<<<cdiv(LL * (SP - SS) * DD, 256), 256>>>(xtph);

    // ================= cross_step attention (padded S -> SP) =================
    launch_gemm<false, 0, 128>(xtph, qkCrossH, nullptr, qkh, LL * SP, QKN, DD, DD, QKN, QKN, 1,
                               0, 0, 0, 0);
    zerof_kernel<<<cdiv(LL * SP, 256), 256>>>(rsum, (long)LL * SP);
    launch_gemm<true, 3, 128>(qkh, qkh + DD4, nullptr, avh, SP, SP, DD4, QKN, QKN, SP, LL,
                              (long)SP * QKN, (long)SP * QKN, 0, (long)SP * SP,
                              scale, nullptr, SP, rsum, SS);
    launch_gemm<false, 4, 256>(avh, xtph, nullptr, scoresh, SS, DD, SP, SP, DD, DD, LL,
                               (long)SP * SP, (long)SP * DD, 0, (long)SS * DD, 0.0f, rsum, SP);
    launch_gemm<false, 0, 256>(scoresh, WvCrossH, nullptr, avh, LL * SS, DD, DD, DD, DD, DD, 1,
                               0, 0, 0, 0);
    ln_kernel<<<LL * SS / 8, 256>>>(xtph, avh, ln2_g, ln2_b, lnh, nullptr, SS,
                                    SP, 1, SS, 1, 1, LL, 0, (long)LL * SS);

    // ================= post_self_step attention =================
    launch_gemm<false, 0, 128>(lnh, qkPostH, nullptr, qkh, LL, QKN, DD, DD, QKN, QKN, SS,
                               LD, (long)DD * QKN, 0, (long)LL * QKN);
    zerof_kernel<<<cdiv(SS * LL, 256), 256>>>(rsum, (long)SS * LL);
    launch_gemm<true, 3, 256>(qkh, qkh + DD4, nullptr, scoresh, LL, LL, DD4, QKN, QKN, LL, SS,
                              (long)LL * QKN, (long)LL * QKN, 0, (long)LL * LL,
                              scale, nullptr, LL, rsum, LL);
    launch_gemm<false, 4, 256>(scoresh, lnh, nullptr, avh, LL, DD, LL, LL, DD, DD, SS,
                               (long)LL * LL, LD, 0, LD, 0.0f, rsum, LL);
    launch_gemm<false, 0, 256>(avh, WvPostH, nullptr, scoresh, LL, DD, DD, DD, DD, DD, SS,
                               LD, (long)DD * DD, 0, LD);
    ln_kernel<<<SS * LL / 8, 256>>>(lnh, scoresh, ln3_g, ln3_b, xh, nullptr, LL,
                                    LL, 1, LL, 1, LL, 1, DD, (long)SS * LL);

    // ================= post_mlp =================
    launch_gemm<false, 2, 192>(xh, W1PostH, post_b1, qkh, LL, DD4, DD, DD, DD4, DD4, SS,
                               LD, (long)DD * DD4, DD4, (long)LL * DD4);
    launch_gemm<false, 1, 256>(qkh, W2PostH, post_b2, scoresh, LL, DD, DD4, DD4, DD, DD, SS,
                               (long)LL * DD4, (long)DD4 * DD, DD, LD);
    ln_kernel<<<SS * LL / 8, 256>>>(xh, scoresh, ln4_g, ln4_b, nullptr, out, LL,
                                    LL, 1, LL, 1, LL, 1, DD, (long)SS * LL);
}

// round 16
// speedup vs baseline: 1.4910x; 1.4910x over previous
#include <cuda_runtime.h>
#include <cuda_fp16.h>
#include <math.h>
#include <stdint.h>

// Problem dims
#define SS 50
#define LL 1024
#define DD 768
#define DD4 192
#define SP 64
#define QKN 384

// ---------------- static scratch (alloc-free rule) ----------------
__device__ __half g_xh[(size_t)SS * LL * DD];
__device__ __half g_lnh[(size_t)SS * LL * DD];
__device__ __half g_xtph[(size_t)LL * SP * DD];
__device__ __half g_qkh[(size_t)LL * SP * QKN];
__device__ __half g_avh[(size_t)SS * LL * DD];
__device__ __half g_scoresh[(size_t)SS * LL * LL];
__device__ float  g_rsum[(size_t)LL * SP];
__device__ __half g_wh[119000000];

// =============== helpers =====================
__device__ __forceinline__ uint32_t smem_u32(const void* p) {
    uint32_t a;
    asm("{ .reg .u64 t; cvta.to.shared.u64 t, %1; cvt.u32.u64 %0, t; }" : "=r"(a) : "l"(p));
    return a;
}
__device__ __forceinline__ void mma_f16(float* d, const uint32_t* a, const uint32_t* b) {
    asm volatile(
        "mma.sync.aligned.m16n8k16.row.col.f32.f16.f16.f32 "
        "{%0,%1,%2,%3}, {%4,%5,%6,%7}, {%8,%9}, {%0,%1,%2,%3};\n"
        : "+f"(d[0]), "+f"(d[1]), "+f"(d[2]), "+f"(d[3])
        : "r"(a[0]), "r"(a[1]), "r"(a[2]), "r"(a[3]),
          "r"(b[0]), "r"(b[1]));
}
__device__ __forceinline__ void ldsm_x4(uint32_t& r0, uint32_t& r1, uint32_t& r2, uint32_t& r3,
                                        uint32_t addr) {
    asm volatile("ldmatrix.sync.aligned.m8n8.x4.shared.b16 {%0,%1,%2,%3}, [%4];"
                 : "=r"(r0), "=r"(r1), "=r"(r2), "=r"(r3) : "r"(addr));
}
__device__ __forceinline__ void ldsm_x4_t(uint32_t& r0, uint32_t& r1, uint32_t& r2, uint32_t& r3,
                                          uint32_t addr) {
    asm volatile("ldmatrix.sync.aligned.m8n8.x4.trans.shared.b16 {%0,%1,%2,%3}, [%4];"
                 : "=r"(r0), "=r"(r1), "=r"(r2), "=r"(r3) : "r"(addr));
}
__device__ __forceinline__ void cp_async16(uint32_t smem_addr, const void* gptr, uint32_t src_bytes) {
    asm volatile("cp.async.ca.shared.global [%0], [%1], 16, %2;"
                 :: "r"(smem_addr), "l"(gptr), "r"(src_bytes));
}
#define CP_COMMIT() asm volatile("cp.async.commit_group;" ::: "memory")
#define CP_WAIT2()  asm volatile("cp.async.wait_group 2;" ::: "memory")

// =================================================================
// cp.async-pipelined FP16 GEMM (mma.sync m16n8k16, ldmatrix frags)
// NT: C = A @ B^T (B [N,K]); NN: C = A @ B (B [K,N], ldmatrix.trans)
// BN in {256, 192, 128}. BM=128.
//   BN=256: warps 2m x 4n, warp 64x64 | BN=192: 2m x 4n, warp 64x48
//   BN=128: warps 4m x 2n, warp 32x64, 2 CTAs/SM
// MODE: 0 plain | 1 +bias | 2 +bias+relu | 3 exp(escale*v) | 4 *rowscale[row]
// fp16 out, fp32 accum.
// =================================================================
#define BMt 128
#define RS 20
#define AWORDS (BMt * RS)
#define NSTAGE 4

template<bool TRANSB, int MODE, int BN>
__global__ __launch_bounds__(256, (BN == 128) ? 2 : 1)
void mma_gemm_kernel(const __half* __restrict__ Ab, const __half* __restrict__ Bb,
                     const float* __restrict__ biasb, __half* __restrict__ Cb,
                     int M, int N, int K, int lda, int ldb, int ldc,
                     long sA, long sB, long sBias, long sC,
                     float escale, const float* __restrict__ rowscale, long sRS)
{
    constexpr bool BIAS = (MODE == 1 || MODE == 2);
    constexpr bool RELU = (MODE == 2);
    constexpr int BWRD = (BN == 256) ? 5120 : (BN == 192) ? 3840 : 2560;
    constexpr int STGW_L = AWORDS + BWRD;
    constexpr int NAM = (BN == 128) ? 2 : 4;
    constexpr int NBN = (BN == 192) ? 6 : 8;
    constexpr int PBN = NBN / 2;
    constexpr int BRS = (BN == 256) ? 132 : (BN == 192) ? 100 : 68;
    constexpr int WN  = (BN == 192) ? 48 : 64;
    constexpr int CH  = BN / 8;
    constexpr int NIT = BN / 64;

    extern __shared__ __align__(16) uint32_t sm[];
    const uint32_t smb = smem_u32(sm);

    const int b = blockIdx.z;
    const __half* A = Ab + (long)b * sA;
    const __half* B = Bb + (long)b * sB;
    __half* C = Cb + (long)b * sC;

    const int brow = blockIdx.y * BMt;
    const int bcol = blockIdx.x * BN;
    const int tid = threadIdx.x;
    const int wid = tid >> 5;
    const int lane = tid & 31;
    const int g = lane >> 2;
    const int c = lane & 3;
    const int warp_m = (BN == 128) ? (wid & 3) * 32 : (wid & 1) * 64;
    const int warp_n = (BN == 128) ? (wid >> 2) * 64 : (wid >> 1) * WN;

    const int a_row  = (lane & 7) + ((lane >> 3) & 1) * 8;
    const int a_koff = ((lane >> 4) & 1) * 8;
    const int bt_row  = (lane & 7) + ((lane >> 4) & 1) * 8;
    const int bt_koff = ((lane >> 3) & 1) * 8;
    const int bn_k = (lane & 7) + ((lane >> 3) & 1) * 8;
    const int bn_n = ((lane >> 4) & 1) * 8;

    const int nkt = K >> 5;

    float acc[NAM][NBN][4];
    #pragma unroll
    for (int i = 0; i < NAM; i++)
        #pragma unroll
        for (int j = 0; j < NBN; j++)
            #pragma unroll
            for (int r = 0; r < 4; r++)
                acc[i][j][r] = 0.0f;

    auto issue_stage = [&](int kt) {
        if (kt < nkt) {
            int k0 = kt << 5;
            uint32_t sbase = smb + ((kt & (NSTAGE - 1)) * STGW_L) * 4;
            #pragma unroll
            for (int i = 0; i < 2; i++) {
                int idx = i * 256 + tid;
                int row = idx >> 2, q = idx & 3;
                int gr = brow + row;
                const __half* gp = A + (long)gr * lda + k0 + q * 8;
                uint32_t dst = sbase + (row * RS + q * 4) * 4;
                cp_async16(dst, gp, (gr < M) ? 16u : 0u);
            }
            if (TRANSB) {
                #pragma unroll
                for (int i = 0; i < NIT; i++) {
                    int idx = i * 256 + tid;
                    int row = idx >> 2, q = idx & 3;
                    int gn = bcol + row;
                    const __half* gp = B + (long)gn * ldb + k0 + q * 8;
                    uint32_t dst = sbase + (AWORDS + row * RS + q * 4) * 4;
                    cp_async16(dst, gp, (gn < N) ? 16u : 0u);
                }
            } else {
                #pragma unroll
                for (int i = 0; i < NIT; i++) {
                    int idx = i * 256 + tid;
                    int kk = idx / CH, ch = idx % CH;
                    int gn = bcol + ch * 8;
                    const __half* gp = B + (long)(k0 + kk) * ldb + gn;
                    uint32_t dst = sbase + (AWORDS + kk * BRS + ch * 4) * 4;
                    cp_async16(dst, gp, (gn < N) ? 16u : 0u);
                }
            }
        }
        CP_COMMIT();
    };

    issue_stage(0);
    issue_stage(1);
    issue_stage(2);

    for (int kt = 0; kt < nkt; kt++) {
        CP_WAIT2();
        __syncthreads();
        issue_stage(kt + 3);

        uint32_t As = smb + ((kt & (NSTAGE - 1)) * STGW_L) * 4;
        uint32_t Bs = As + AWORDS * 4;

        #pragma unroll
        for (int ks = 0; ks < 2; ks++) {
            int kh = ks * 16;
            uint32_t af[NAM][4], bf[NBN][2];
            #pragma unroll
            for (int am = 0; am < NAM; am++) {
                uint32_t addr = As + ((warp_m + am * 16 + a_row) * RS) * 4
                                   + (kh + a_koff) * 2;
                ldsm_x4(af[am][0], af[am][1], af[am][2], af[am][3], addr);
            }
            #pragma unroll
            for (int p = 0; p < PBN; p++) {
                if (TRANSB) {
                    uint32_t addr = Bs + ((warp_n + p * 16 + bt_row) * RS) * 4
                                       + (kh + bt_koff) * 2;
                    ldsm_x4(bf[2 * p][0], bf[2 * p][1], bf[2 * p + 1][0], bf[2 * p + 1][1], addr);
                } else {
                    uint32_t addr = Bs + ((kh + bn_k) * BRS) * 4
                                       + (warp_n + p * 16 + bn_n) * 2;
                    ldsm_x4_t(bf[2 * p][0], bf[2 * p][1], bf[2 * p + 1][0], bf[2 * p + 1][1], addr);
                }
            }
            #pragma unroll
            for (int am = 0; am < NAM; am++)
                #pragma unroll
                for (int bn = 0; bn < NBN; bn++)
                    mma_f16(acc[am][bn], af[am], bf[bn]);
        }
    }

    // ---- epilogue (fp16 out) ----
    #pragma unroll
    for (int am = 0; am < NAM; am++) {
        int row0 = brow + warp_m + am * 16 + g;
        float rs0 = 1.0f, rs1 = 1.0f;
        if (MODE == 4) {
            rs0 = (row0 < M)     ? rowscale[(long)b * sRS + row0]     : 0.0f;
            rs1 = (row0 + 8 < M) ? rowscale[(long)b * sRS + row0 + 8] : 0.0f;
        }
        #pragma unroll
        for (int bn = 0; bn < NBN; bn++) {
            int col = bcol + warp_n + bn * 8 + c * 2;
            if (col >= N) continue;
            float v0 = acc[am][bn][0], v1 = acc[am][bn][1];
            float v2 = acc[am][bn][2], v3 = acc[am][bn][3];
            if (BIAS) {
                float b0 = biasb[(long)b * sBias + col];
                float b1 = biasb[(long)b * sBias + col + 1];
                v0 += b0; v1 += b1; v2 += b0; v3 += b1;
            }
            if (RELU) {
                v0 = fmaxf(v0, 0.f); v1 = fmaxf(v1, 0.f);
                v2 = fmaxf(v2, 0.f); v3 = fmaxf(v3, 0.f);
            }
            if (MODE == 3) {
                v0 = __expf(v0 * escale); v1 = __expf(v1 * escale);
                v2 = __expf(v2 * escale); v3 = __expf(v3 * escale);
            }
            if (MODE == 4) {
                v0 *= rs0; v1 *= rs0; v2 *= rs1; v3 *= rs1;
            }
            __half2 h01 = __floats2half2_rn(v0, v1);
            __half2 h23 = __floats2half2_rn(v2, v3);
            if (row0 < M)     *(__half2*)&C[(long)row0 * ldc + col]       = h01;
            if (row0 + 8 < M) *(__half2*)&C[(long)(row0 + 8) * ldc + col] = h23;
        }
    }
}

// ---------------- float -> half elementwise ----------------
__global__ __launch_bounds__(256)
void f2h_kernel(const float* __restrict__ in, __half* __restrict__ out, long n4)
{
    long i = (long)blockIdx.x * 256 + threadIdx.x;
    if (i >= n4) return;
    float4 v = ((const float4*)in)[i];
    ((__half2*)out)[i * 2]     = __floats2half2_rn(v.x, v.y);
    ((__half2*)out)[i * 2 + 1] = __floats2half2_rn(v.z, v.w);
}

// ------- concat Wq||Wk -> half [batch, D, QKN] --------
__global__ __launch_bounds__(256)
void concat_qk_kernel(const float* __restrict__ Wq, const float* __restrict__ Wk,
                      __half* __restrict__ out, long total)
{
    long i = (long)blockIdx.x * 256 + threadIdx.x;
    if (i >= total) return;
    long j = i % QKN;
    long bd = i / QKN;
    float v = (j < DD4) ? Wq[bd * DD4 + j] : Wk[bd * DD4 + (j - DD4)];
    out[i] = __float2half_rn(v);
}

// ------- warp-per-row reciprocal row sum (+ zero pad cols) --------
__global__ __launch_bounds__(256)
void rowsum_kernel(__half* __restrict__ data, float* __restrict__ rsum,
                   int n, int stride, long nrows)
{
    int wid = threadIdx.x >> 5, lane = threadIdx.x & 31;
    long row = (long)blockIdx.x * 8 + wid;
    if (row >= nrows) return;
    __half2* p2 = (__half2*)(data + row * (long)stride);
    int n2 = n >> 1;

    float s = 0.0f;
    for (int i = lane; i < n2; i += 32) {
        float2 v = __half22float2(p2[i]);
        s += v.x + v.y;
    }
    #pragma unroll
    for (int o = 16; o > 0; o >>= 1) s += __shfl_xor_sync(0xffffffffu, s, o);
    if (lane == 0) rsum[row] = 1.0f / s;

    int s2 = stride >> 1;
    for (int i = n2 + lane; i < s2; i += 32) p2[i] = __floats2half2_rn(0.f, 0.f);
}

// ------ warp-per-row fused residual + LayerNorm (fp16 stream, fp32 math) ------
__global__ __launch_bounds__(256)
void ln_kernel(const __half* __restrict__ resid, const __half* __restrict__ h,
               const float* __restrict__ gam, const float* __restrict__ bet,
               __half* __restrict__ outh, float* __restrict__ outf, int J,
               long ri, long rj, long hi, long hj, long oi, long oj, long gstride,
               long nrows)
{
    int wid = threadIdx.x >> 5, lane = threadIdx.x & 31;
    long row = (long)blockIdx.x * 8 + wid;
    if (row >= nrows) return;
    long i = row / J, j = row % J;
    const __half2* r2 = (const __half2*)(resid + (i * ri + j * rj) * DD);
    const __half2* h2 = (const __half2*)(h     + (i * hi + j * hj) * DD);
    long orow = i * oi + j * oj;
    const float2* gp = (const float2*)(gam + i * gstride);
    const float2* bp = (const float2*)(bet + i * gstride);

    float2 v[12];
    float s = 0.0f, s2 = 0.0f;
    #pragma unroll
    for (int k = 0; k < 12; k++) {
        int d = lane + k * 32;
        float2 a = __half22float2(r2[d]);
        float2 b = __half22float2(h2[d]);
        float2 val = make_float2(a.x + b.x, a.y + b.y);
        v[k] = val;
        s += val.x + val.y;
        s2 += val.x * val.x + val.y * val.y;
    }
    #pragma unroll
    for (int o = 16; o > 0; o >>= 1) {
        s  += __shfl_xor_sync(0xffffffffu, s, o);
        s2 += __shfl_xor_sync(0xffffffffu, s2, o);
    }
    float mean = s * (1.0f / DD);
    float var  = s2 * (1.0f / DD) - mean * mean;
    float inv  = rsqrtf(var + 1e-5f);

    #pragma unroll
    for (int k = 0; k < 12; k++) {
        int d = lane + k * 32;
        float2 gg = gp[d], bb = bp[d];
        float o0 = (v[k].x - mean) * inv * gg.x + bb.x;
        float o1 = (v[k].y - mean) * inv * gg.y + bb.y;
        if (outh) ((__half2*)(outh + orow * DD))[d] = __floats2half2_rn(o0, o1);
        if (outf) ((float2*)(outf + orow * DD))[d] = make_float2(o0, o1);
    }
}

// ---------------- zero pad rows of xtph [LL, SP, DD] ----------------
__global__ __launch_bounds__(256)
void zero_pad_kernel(__half* __restrict__ xth)
{
    long idx = (long)blockIdx.x * 256 + threadIdx.x;
    const long per_l = (long)(SP - SS) * DD;
    const long total = (long)LL * per_l;
    if (idx >= total) return;
    long l = idx / per_l;
    long off = idx % per_l;
    xth[((long)l * SP + SS) * DD + off] = __float2half_rn(0.0f);
}

// ---------------- launch plumbing ----------------
static inline int cdiv(int a, int b) { return (a + b - 1) / b; }

template<bool TRANSB, int MODE, int BN>
static void launch_gemm(const __half* A, const __half* B, const float* bias, __half* C,
                        int M, int N, int K, int lda, int ldb, int ldc, int batch,
                        long sA, long sB, long sBias, long sC,
                        float escale = 0.0f, const float* rowscale = nullptr, long sRS = 0)
{
    const int BWRD = (BN == 256) ? 5120 : (BN == 192) ? 3840 : 2560;
    const int smem = (AWORDS + BWRD) * NSTAGE * 4;
    dim3 grid(cdiv(N, BN), cdiv(M, BMt), batch);
    cudaFuncSetAttribute(mma_gemm_kernel<TRANSB, MODE, BN>,
                         cudaFuncAttributeMaxDynamicSharedMemorySize, smem);
    mma_gemm_kernel<TRANSB, MODE, BN><<<grid, 256, smem>>>(
        A, B, bias, C, M, N, K, lda, ldb, ldc, sA, sB, sBias, sC, escale, rowscale, sRS);
}

extern "C" void kernel_launch(void* const* d_in, const int* in_sizes, int n_in,
                              void* d_out, int out_size)
{
    (void)in_sizes; (void)n_in; (void)out_size;

    const float* x        = (const float*)d_in[0];
    const float* pre_Wq   = (const float*)d_in[1];
    const float* pre_Wk   = (const float*)d_in[2];
    const float* pre_Wv   = (const float*)d_in[3];
    const float* ln1_g    = (const float*)d_in[4];
    const float* ln1_b    = (const float*)d_in[5];
    const float* pre_W1   = (const float*)d_in[6];
    const float* pre_b1   = (const float*)d_in[7];
    const float* pre_W2   = (const float*)d_in[8];
    const float* pre_b2   = (const float*)d_in[9];
    const float* ln4p_g   = (const float*)d_in[10];
    const float* ln4p_b   = (const float*)d_in[11];
    const float* cross_Wq = (const float*)d_in[12];
    const float* cross_Wk = (const float*)d_in[13];
    const float* cross_Wv = (const float*)d_in[14];
    const float* ln2_g    = (const float*)d_in[15];
    const float* ln2_b    = (const float*)d_in[16];
    const float* post_Wq  = (const float*)d_in[17];
    const float* post_Wk  = (const float*)d_in[18];
    const float* post_Wv  = (const float*)d_in[19];
    const float* ln3_g    = (const float*)d_in[20];
    const float* ln3_b    = (const float*)d_in[21];
    const float* post_W1  = (const float*)d_in[22];
    const float* post_b1  = (const float*)d_in[23];
    const float* post_W2  = (const float*)d_in[24];
    const float* post_b2  = (const float*)d_in[25];
    const float* ln4_g    = (const float*)d_in[26];
    const float* ln4_b    = (const float*)d_in[27];
    float* out = (float*)d_out;

    __half *xh, *lnh, *xtph, *qkh, *avh, *scoresh, *wh;
    float* rsum;
    cudaGetSymbolAddress((void**)&xh, g_xh);
    cudaGetSymbolAddress((void**)&lnh, g_lnh);
    cudaGetSymbolAddress((void**)&xtph, g_xtph);
    cudaGetSymbolAddress((void**)&qkh, g_qkh);
    cudaGetSymbolAddress((void**)&avh, g_avh);
    cudaGetSymbolAddress((void**)&scoresh, g_scoresh);
    cudaGetSymbolAddress((void**)&rsum, g_rsum);
    cudaGetSymbolAddress((void**)&wh, g_wh);

    const long SZ_QKW = (long)SS * DD * QKN;
    const long SZ_VW  = (long)SS * DD * DD;
    const long SZ_W1  = (long)SS * DD * DD4;
    __half* qkPreH   = wh;
    __half* qkPostH  = qkPreH  + SZ_QKW;
    __half* qkCrossH = qkPostH + SZ_QKW;
    __half* WvPreH   = qkCrossH + (long)DD * QKN;
    __half* WvPostH  = WvPreH  + SZ_VW;
    __half* WvCrossH = WvPostH + SZ_VW;
    __half* W1PreH   = WvCrossH + (long)DD * DD;
    __half* W1PostH  = W1PreH  + SZ_W1;
    __half* W2PreH   = W1PostH + SZ_W1;
    __half* W2PostH  = W2PreH  + SZ_W1;

    const float scale = 1.0f / sqrtf((float)DD4);
    const long LD = (long)LL * DD;

    // ---------------- weight prep: pure streaming f2h / concat ----------
    concat_qk_kernel<<<cdiv((int)SZ_QKW, 256), 256>>>(pre_Wq, pre_Wk, qkPreH, SZ_QKW);
    concat_qk_kernel<<<cdiv((int)SZ_QKW, 256), 256>>>(post_Wq, post_Wk, qkPostH, SZ_QKW);
    concat_qk_kernel<<<cdiv((int)(DD * QKN), 256), 256>>>(cross_Wq, cross_Wk, qkCrossH, (long)DD * QKN);
    f2h_kernel<<<cdiv((int)(SZ_VW / 4), 256), 256>>>(pre_Wv,  WvPreH,  SZ_VW / 4);
    f2h_kernel<<<cdiv((int)(SZ_VW / 4), 256), 256>>>(post_Wv, WvPostH, SZ_VW / 4);
    f2h_kernel<<<cdiv((int)((long)DD * DD / 4), 256), 256>>>(cross_Wv, WvCrossH, (long)DD * DD / 4);
    f2h_kernel<<<cdiv((int)(SZ_W1 / 4), 256), 256>>>(pre_W1,  W1PreH,  SZ_W1 / 4);
    f2h_kernel<<<cdiv((int)(SZ_W1 / 4), 256), 256>>>(post_W1, W1PostH, SZ_W1 / 4);
    f2h_kernel<<<cdiv((int)(SZ_W1 / 4), 256), 256>>>(pre_W2,  W2PreH,  SZ_W1 / 4);
    f2h_kernel<<<cdiv((int)(SZ_W1 / 4), 256), 256>>>(post_W2, W2PostH, SZ_W1 / 4);
    f2h_kernel<<<cdiv((int)(SS * LD / 4), 256), 256>>>(x, xh, SS * LD / 4);

    // ================= pre_self_step attention =================
    launch_gemm<false, 0, 128>(xh, qkPreH, nullptr, qkh, LL, QKN, DD, DD, QKN, QKN, SS,
                               LD, (long)DD * QKN, 0, (long)LL * QKN);
    launch_gemm<true, 3, 256>(qkh, qkh + DD4, nullptr, scoresh, LL, LL, DD4, QKN, QKN, LL, SS,
                              (long)LL * QKN, (long)LL * QKN, 0, (long)LL * LL, scale);
    rowsum_kernel<<<SS * LL / 8, 256>>>(scoresh, rsum, LL, LL, (long)SS * LL);
    launch_gemm<false, 4, 256>(scoresh, xh, nullptr, avh, LL, DD, LL, LL, DD, DD, SS,
                               (long)LL * LL, LD, 0, LD, 0.0f, rsum, LL);
    launch_gemm<false, 0, 256>(avh, WvPreH, nullptr, scoresh, LL, DD, DD, DD, DD, DD, SS,
                               LD, (long)DD * DD, 0, LD);
    ln_kernel<<<SS * LL / 8, 256>>>(xh, scoresh, ln1_g, ln1_b, lnh, nullptr, LL,
                                    LL, 1, LL, 1, LL, 1, DD, (long)SS * LL);

    // ================= pre_mlp =================
    launch_gemm<false, 2, 192>(lnh, W1PreH, pre_b1, qkh, LL, DD4, DD, DD, DD4, DD4, SS,
                               LD, (long)DD * DD4, DD4, (long)LL * DD4);
    launch_gemm<false, 1, 256>(qkh, W2PreH, pre_b2, scoresh, LL, DD, DD4, DD4, DD, DD, SS,
                               (long)LL * DD4, (long)DD4 * DD, DD, LD);
    ln_kernel<<<SS * LL / 8, 256>>>(lnh, scoresh, ln4p_g, ln4p_b, xtph, nullptr, LL,
                                    LL, 1, LL, 1, 1, SP, DD, (long)SS * LL);
    zero_pad_kernel<<<cdiv(LL * (SP - SS) * DD, 256), 256>>>(xtph);

    // ================= cross_step attention (padded S -> SP) =================
    launch_gemm<false, 0, 128>(xtph, qkCrossH, nullptr, qkh, LL * SP, QKN, DD, DD, QKN, QKN, 1,
                               0, 0, 0, 0);
    launch_gemm<true, 3, 128>(qkh, qkh + DD4, nullptr, avh, SP, SP, DD4, QKN, QKN, SP, LL,
                              (long)SP * QKN, (long)SP * QKN, 0, (long)SP * SP, scale);
    rowsum_kernel<<<LL * SP / 8, 256>>>(avh, rsum, SS, SP, (long)LL * SP);
    launch_gemm<false, 4, 256>(avh, xtph, nullptr, scoresh, SS, DD, SP, SP, DD, DD, LL,
                               (long)SP * SP, (long)SP * DD, 0, (long)SS * DD, 0.0f, rsum, SP);
    launch_gemm<false, 0, 256>(scoresh, WvCrossH, nullptr, avh, LL * SS, DD, DD, DD, DD, DD, 1,
                               0, 0, 0, 0);
    ln_kernel<<<LL * SS / 8, 256>>>(xtph, avh, ln2_g, ln2_b, lnh, nullptr, SS,
                                    SP, 1, SS, 1, 1, LL, 0, (long)LL * SS);

    // ================= post_self_step attention =================
    launch_gemm<false, 0, 128>(lnh, qkPostH, nullptr, qkh, LL, QKN, DD, DD, QKN, QKN, SS,
                               LD, (long)DD * QKN, 0, (long)LL * QKN);
    launch_gemm<true, 3, 256>(qkh, qkh + DD4, nullptr, scoresh, LL, LL, DD4, QKN, QKN, LL, SS,
                              (long)LL * QKN, (long)LL * QKN, 0, (long)LL * LL, scale);
    rowsum_kernel<<<SS * LL / 8, 256>>>(scoresh, rsum, LL, LL, (long)SS * LL);
    launch_gemm<false, 4, 256>(scoresh, lnh, nullptr, avh, LL, DD, LL, LL, DD, DD, SS,
                               (long)LL * LL, LD, 0, LD, 0.0f, rsum, LL);
    launch_gemm<false, 0, 256>(avh, WvPostH, nullptr, scoresh, LL, DD, DD, DD, DD, DD, SS,
                               LD, (long)DD * DD, 0, LD);
    ln_kernel<<<SS * LL / 8, 256>>>(lnh, scoresh, ln3_g, ln3_b, xh, nullptr, LL,
                                    LL, 1, LL, 1, LL, 1, DD, (long)SS * LL);

    // ================= post_mlp =================
    launch_gemm<false, 2, 192>(xh, W1PostH, post_b1, qkh, LL, DD4, DD, DD, DD4, DD4, SS,
                               LD, (long)DD * DD4, DD4, (long)LL * DD4);
    launch_gemm<false, 1, 256>(qkh, W2PostH, post_b2, scoresh, LL, DD, DD4, DD4, DD, DD, SS,
                               (long)LL * DD4, (long)DD4 * DD, DD, LD);
    ln_kernel<<<SS * LL / 8, 256>>>(xh, scoresh, ln4_g, ln4_b, nullptr, out, LL,
                                    LL, 1, LL, 1, LL, 1, DD, (long)SS * LL);
}

// round 17
// speedup vs baseline: 1.4926x; 1.0011x over previous
#include <cuda_runtime.h>
#include <cuda_fp16.h>
#include <math.h>
#include <stdint.h>

// Problem dims
#define SS 50
#define LL 1024
#define DD 768
#define DD4 192
#define SP 64
#define QKN 384

// ---------------- static scratch (alloc-free rule) ----------------
__device__ __half g_xh[(size_t)SS * LL * DD];
__device__ __half g_lnh[(size_t)SS * LL * DD];
__device__ __half g_xtph[(size_t)LL * SP * DD];
__device__ __half g_qkh[(size_t)LL * SP * QKN];
__device__ __half g_avh[(size_t)SS * LL * DD];
__device__ __half g_scoresh[(size_t)SS * LL * LL];
__device__ float  g_rsum[(size_t)LL * SP];
__device__ __half g_wh[119000000];

// =============== helpers =====================
__device__ __forceinline__ uint32_t smem_u32(const void* p) {
    uint32_t a;
    asm("{ .reg .u64 t; cvta.to.shared.u64 t, %1; cvt.u32.u64 %0, t; }" : "=r"(a) : "l"(p));
    return a;
}
__device__ __forceinline__ void mma_f16(float* d, const uint32_t* a, const uint32_t* b) {
    asm volatile(
        "mma.sync.aligned.m16n8k16.row.col.f32.f16.f16.f32 "
        "{%0,%1,%2,%3}, {%4,%5,%6,%7}, {%8,%9}, {%0,%1,%2,%3};\n"
        : "+f"(d[0]), "+f"(d[1]), "+f"(d[2]), "+f"(d[3])
        : "r"(a[0]), "r"(a[1]), "r"(a[2]), "r"(a[3]),
          "r"(b[0]), "r"(b[1]));
}
__device__ __forceinline__ void ldsm_x4(uint32_t& r0, uint32_t& r1, uint32_t& r2, uint32_t& r3,
                                        uint32_t addr) {
    asm volatile("ldmatrix.sync.aligned.m8n8.x4.shared.b16 {%0,%1,%2,%3}, [%4];"
                 : "=r"(r0), "=r"(r1), "=r"(r2), "=r"(r3) : "r"(addr));
}
__device__ __forceinline__ void ldsm_x4_t(uint32_t& r0, uint32_t& r1, uint32_t& r2, uint32_t& r3,
                                          uint32_t addr) {
    asm volatile("ldmatrix.sync.aligned.m8n8.x4.trans.shared.b16 {%0,%1,%2,%3}, [%4];"
                 : "=r"(r0), "=r"(r1), "=r"(r2), "=r"(r3) : "r"(addr));
}
__device__ __forceinline__ void cp_async16(uint32_t smem_addr, const void* gptr, uint32_t src_bytes) {
    asm volatile("cp.async.ca.shared.global [%0], [%1], 16, %2;"
                 :: "r"(smem_addr), "l"(gptr), "r"(src_bytes));
}
#define CP_COMMIT() asm volatile("cp.async.commit_group;" ::: "memory")
#define CP_WAIT2()  asm volatile("cp.async.wait_group 2;" ::: "memory")

// =================================================================
// cp.async-pipelined FP16 GEMM (mma.sync m16n8k16, ldmatrix frags)
// NT: C = A @ B^T (B [N,K]); NN: C = A @ B (B [K,N], ldmatrix.trans)
// BN in {256, 192, 128}. BM=128.
//   BN=256: warps 2m x 4n, warp 64x64 | BN=192: 2m x 4n, warp 64x48
//   BN=128: warps 4m x 2n, warp 32x64, 2 CTAs/SM
// MODE: 0 plain | 1 +bias | 2 +bias+relu | 3 exp(escale*v) | 4 *rowscale[row]
// fp16 out, fp32 accum.
// =================================================================
#define BMt 128
#define RS 20
#define AWORDS (BMt * RS)
#define NSTAGE 4

template<bool TRANSB, int MODE, int BN>
__global__ __launch_bounds__(256, (BN == 128) ? 2 : 1)
void mma_gemm_kernel(const __half* __restrict__ Ab, const __half* __restrict__ Bb,
                     const float* __restrict__ biasb, __half* __restrict__ Cb,
                     int M, int N, int K, int lda, int ldb, int ldc,
                     long sA, long sB, long sBias, long sC,
                     float escale, const float* __restrict__ rowscale, long sRS)
{
    constexpr bool BIAS = (MODE == 1 || MODE == 2);
    constexpr bool RELU = (MODE == 2);
    constexpr int BWRD = (BN == 256) ? 5120 : (BN == 192) ? 3840 : 2560;
    constexpr int STGW_L = AWORDS + BWRD;
    constexpr int NAM = (BN == 128) ? 2 : 4;
    constexpr int NBN = (BN == 192) ? 6 : 8;
    constexpr int PBN = NBN / 2;
    constexpr int BRS = (BN == 256) ? 132 : (BN == 192) ? 100 : 68;
    constexpr int WN  = (BN == 192) ? 48 : 64;
    constexpr int CH  = BN / 8;
    constexpr int NIT = BN / 64;

    extern __shared__ __align__(16) uint32_t sm[];
    const uint32_t smb = smem_u32(sm);

    const int b = blockIdx.z;
    const __half* A = Ab + (long)b * sA;
    const __half* B = Bb + (long)b * sB;
    __half* C = Cb + (long)b * sC;

    const int brow = blockIdx.y * BMt;
    const int bcol = blockIdx.x * BN;
    const int tid = threadIdx.x;
    const int wid = tid >> 5;
    const int lane = tid & 31;
    const int g = lane >> 2;
    const int c = lane & 3;
    const int warp_m = (BN == 128) ? (wid & 3) * 32 : (wid & 1) * 64;
    const int warp_n = (BN == 128) ? (wid >> 2) * 64 : (wid >> 1) * WN;

    const int a_row  = (lane & 7) + ((lane >> 3) & 1) * 8;
    const int a_koff = ((lane >> 4) & 1) * 8;
    const int bt_row  = (lane & 7) + ((lane >> 4) & 1) * 8;
    const int bt_koff = ((lane >> 3) & 1) * 8;
    const int bn_k = (lane & 7) + ((lane >> 3) & 1) * 8;
    const int bn_n = ((lane >> 4) & 1) * 8;

    const int nkt = K >> 5;

    float acc[NAM][NBN][4];
    #pragma unroll
    for (int i = 0; i < NAM; i++)
        #pragma unroll
        for (int j = 0; j < NBN; j++)
            #pragma unroll
            for (int r = 0; r < 4; r++)
                acc[i][j][r] = 0.0f;

    auto issue_stage = [&](int kt) {
        if (kt < nkt) {
            int k0 = kt << 5;
            uint32_t sbase = smb + ((kt & (NSTAGE - 1)) * STGW_L) * 4;
            #pragma unroll
            for (int i = 0; i < 2; i++) {
                int idx = i * 256 + tid;
                int row = idx >> 2, q = idx & 3;
                int gr = brow + row;
                const __half* gp = A + (long)gr * lda + k0 + q * 8;
                uint32_t dst = sbase + (row * RS + q * 4) * 4;
                cp_async16(dst, gp, (gr < M) ? 16u : 0u);
            }
            if (TRANSB) {
                #pragma unroll
                for (int i = 0; i < NIT; i++) {
                    int idx = i * 256 + tid;
                    int row = idx >> 2, q = idx & 3;
                    int gn = bcol + row;
                    const __half* gp = B + (long)gn * ldb + k0 + q * 8;
                    uint32_t dst = sbase + (AWORDS + row * RS + q * 4) * 4;
                    cp_async16(dst, gp, (gn < N) ? 16u : 0u);
                }
            } else {
                #pragma unroll
                for (int i = 0; i < NIT; i++) {
                    int idx = i * 256 + tid;
                    int kk = idx / CH, ch = idx % CH;
                    int gn = bcol + ch * 8;
                    const __half* gp = B + (long)(k0 + kk) * ldb + gn;
                    uint32_t dst = sbase + (AWORDS + kk * BRS + ch * 4) * 4;
                    cp_async16(dst, gp, (gn < N) ? 16u : 0u);
                }
            }
        }
        CP_COMMIT();
    };

    issue_stage(0);
    issue_stage(1);
    issue_stage(2);

    for (int kt = 0; kt < nkt; kt++) {
        CP_WAIT2();
        __syncthreads();
        issue_stage(kt + 3);

        uint32_t As = smb + ((kt & (NSTAGE - 1)) * STGW_L) * 4;
        uint32_t Bs = As + AWORDS * 4;

        #pragma unroll
        for (int ks = 0; ks < 2; ks++) {
            int kh = ks * 16;
            uint32_t af[NAM][4], bf[NBN][2];
            #pragma unroll
            for (int am = 0; am < NAM; am++) {
                uint32_t addr = As + ((warp_m + am * 16 + a_row) * RS) * 4
                                   + (kh + a_koff) * 2;
                ldsm_x4(af[am][0], af[am][1], af[am][2], af[am][3], addr);
            }
            #pragma unroll
            for (int p = 0; p < PBN; p++) {
                if (TRANSB) {
                    uint32_t addr = Bs + ((warp_n + p * 16 + bt_row) * RS) * 4
                                       + (kh + bt_koff) * 2;
                    ldsm_x4(bf[2 * p][0], bf[2 * p][1], bf[2 * p + 1][0], bf[2 * p + 1][1], addr);
                } else {
                    uint32_t addr = Bs + ((kh + bn_k) * BRS) * 4
                                       + (warp_n + p * 16 + bn_n) * 2;
                    ldsm_x4_t(bf[2 * p][0], bf[2 * p][1], bf[2 * p + 1][0], bf[2 * p + 1][1], addr);
                }
            }
            #pragma unroll
            for (int am = 0; am < NAM; am++)
                #pragma unroll
                for (int bn = 0; bn < NBN; bn++)
                    mma_f16(acc[am][bn], af[am], bf[bn]);
        }
    }

    // ---- epilogue (fp16 out) ----
    #pragma unroll
    for (int am = 0; am < NAM; am++) {
        int row0 = brow + warp_m + am * 16 + g;
        float rs0 = 1.0f, rs1 = 1.0f;
        if (MODE == 4) {
            rs0 = (row0 < M)     ? rowscale[(long)b * sRS + row0]     : 0.0f;
            rs1 = (row0 + 8 < M) ? rowscale[(long)b * sRS + row0 + 8] : 0.0f;
        }
        #pragma unroll
        for (int bn = 0; bn < NBN; bn++) {
            int col = bcol + warp_n + bn * 8 + c * 2;
            if (col >= N) continue;
            float v0 = acc[am][bn][0], v1 = acc[am][bn][1];
            float v2 = acc[am][bn][2], v3 = acc[am][bn][3];
            if (BIAS) {
                float b0 = biasb[(long)b * sBias + col];
                float b1 = biasb[(long)b * sBias + col + 1];
                v0 += b0; v1 += b1; v2 += b0; v3 += b1;
            }
            if (RELU) {
                v0 = fmaxf(v0, 0.f); v1 = fmaxf(v1, 0.f);
                v2 = fmaxf(v2, 0.f); v3 = fmaxf(v3, 0.f);
            }
            if (MODE == 3) {
                v0 = __expf(v0 * escale); v1 = __expf(v1 * escale);
                v2 = __expf(v2 * escale); v3 = __expf(v3 * escale);
            }
            if (MODE == 4) {
                v0 *= rs0; v1 *= rs0; v2 *= rs1; v3 *= rs1;
            }
            __half2 h01 = __floats2half2_rn(v0, v1);
            __half2 h23 = __floats2half2_rn(v2, v3);
            if (row0 < M)     *(__half2*)&C[(long)row0 * ldc + col]       = h01;
            if (row0 + 8 < M) *(__half2*)&C[(long)(row0 + 8) * ldc + col] = h23;
        }
    }
}

// ---------------- float -> half elementwise ----------------
__global__ __launch_bounds__(256)
void f2h_kernel(const float* __restrict__ in, __half* __restrict__ out, long n4)
{
    long i = (long)blockIdx.x * 256 + threadIdx.x;
    if (i >= n4) return;
    float4 v = ((const float4*)in)[i];
    ((__half2*)out)[i * 2]     = __floats2half2_rn(v.x, v.y);
    ((__half2*)out)[i * 2 + 1] = __floats2half2_rn(v.z, v.w);
}

// ------- concat Wq||Wk -> half [batch, D, QKN] --------
__global__ __launch_bounds__(256)
void concat_qk_kernel(const float* __restrict__ Wq, const float* __restrict__ Wk,
                      __half* __restrict__ out, long total)
{
    long i = (long)blockIdx.x * 256 + threadIdx.x;
    if (i >= total) return;
    long j = i % QKN;
    long bd = i / QKN;
    float v = (j < DD4) ? Wq[bd * DD4 + j] : Wk[bd * DD4 + (j - DD4)];
    out[i] = __float2half_rn(v);
}

// ------- warp-per-row reciprocal row sum (+ zero pad cols) --------
__global__ __launch_bounds__(256)
void rowsum_kernel(__half* __restrict__ data, float* __restrict__ rsum,
                   int n, int stride, long nrows)
{
    int wid = threadIdx.x >> 5, lane = threadIdx.x & 31;
    long row = (long)blockIdx.x * 8 + wid;
    if (row >= nrows) return;
    __half2* p2 = (__half2*)(data + row * (long)stride);
    int n2 = n >> 1;

    float s = 0.0f;
    for (int i = lane; i < n2; i += 32) {
        float2 v = __half22float2(p2[i]);
        s += v.x + v.y;
    }
    #pragma unroll
    for (int o = 16; o > 0; o >>= 1) s += __shfl_xor_sync(0xffffffffu, s, o);
    if (lane == 0) rsum[row] = 1.0f / s;

    int s2 = stride >> 1;
    for (int i = n2 + lane; i < s2; i += 32) p2[i] = __floats2half2_rn(0.f, 0.f);
}

// ------ warp-per-row fused residual + LayerNorm (fp16 stream, fp32 math) ------
__global__ __launch_bounds__(256)
void ln_kernel(const __half* __restrict__ resid, const __half* __restrict__ h,
               const float* __restrict__ gam, const float* __restrict__ bet,
               __half* __restrict__ outh, float* __restrict__ outf, int J,
               long ri, long rj, long hi, long hj, long oi, long oj, long gstride,
               long nrows)
{
    int wid = threadIdx.x >> 5, lane = threadIdx.x & 31;
    long row = (long)blockIdx.x * 8 + wid;
    if (row >= nrows) return;
    long i = row / J, j = row % J;
    const __half2* r2 = (const __half2*)(resid + (i * ri + j * rj) * DD);
    const __half2* h2 = (const __half2*)(h     + (i * hi + j * hj) * DD);
    long orow = i * oi + j * oj;
    const float2* gp = (const float2*)(gam + i * gstride);
    const float2* bp = (const float2*)(bet + i * gstride);

    float2 v[12];
    float s = 0.0f, s2 = 0.0f;
    #pragma unroll
    for (int k = 0; k < 12; k++) {
        int d = lane + k * 32;
        float2 a = __half22float2(r2[d]);
        float2 b = __half22float2(h2[d]);
        float2 val = make_float2(a.x + b.x, a.y + b.y);
        v[k] = val;
        s += val.x + val.y;
        s2 += val.x * val.x + val.y * val.y;
    }
    #pragma unroll
    for (int o = 16; o > 0; o >>= 1) {
        s  += __shfl_xor_sync(0xffffffffu, s, o);
        s2 += __shfl_xor_sync(0xffffffffu, s2, o);
    }
    float mean = s * (1.0f / DD);
    float var  = s2 * (1.0f / DD) - mean * mean;
    float inv  = rsqrtf(var + 1e-5f);

    #pragma unroll
    for (int k = 0; k < 12; k++) {
        int d = lane + k * 32;
        float2 gg = gp[d], bb = bp[d];
        float o0 = (v[k].x - mean) * inv * gg.x + bb.x;
        float o1 = (v[k].y - mean) * inv * gg.y + bb.y;
        if (outh) ((__half2*)(outh + orow * DD))[d] = __floats2half2_rn(o0, o1);
        if (outf) ((float2*)(outf + orow * DD))[d] = make_float2(o0, o1);
    }
}

// ---------------- zero pad rows of xtph [LL, SP, DD] ----------------
__global__ __launch_bounds__(256)
void zero_pad_kernel(__half* __restrict__ xth)
{
    long idx = (long)blockIdx.x * 256 + threadIdx.x;
    const long per_l = (long)(SP - SS) * DD;
    const long total = (long)LL * per_l;
    if (idx >= total) return;
    long l = idx / per_l;
    long off = idx % per_l;
    xth[((long)l * SP + SS) * DD + off] = __float2half_rn(0.0f);
}

// ---------------- launch plumbing ----------------
static inline int cdiv(int a, int b) { return (a + b - 1) / b; }

template<bool TRANSB, int MODE, int BN>
static void launch_gemm(const __half* A, const __half* B, const float* bias, __half* C,
                        int M, int N, int K, int lda, int ldb, int ldc, int batch,
                        long sA, long sB, long sBias, long sC,
                        float escale = 0.0f, const float* rowscale = nullptr, long sRS = 0)
{
    const int BWRD = (BN == 256) ? 5120 : (BN == 192) ? 3840 : 2560;
    const int smem = (AWORDS + BWRD) * NSTAGE * 4;
    dim3 grid(cdiv(N, BN), cdiv(M, BMt), batch);
    cudaFuncSetAttribute(mma_gemm_kernel<TRANSB, MODE, BN>,
                         cudaFuncAttributeMaxDynamicSharedMemorySize, smem);
    mma_gemm_kernel<TRANSB, MODE, BN><<<grid, 256, smem>>>(
        A, B, bias, C, M, N, K, lda, ldb, ldc, sA, sB, sBias, sC, escale, rowscale, sRS);
}

extern "C" void kernel_launch(void* const* d_in, const int* in_sizes, int n_in,
                              void* d_out, int out_size)
{
    (void)in_sizes; (void)n_in; (void)out_size;

    const float* x        = (const float*)d_in[0];
    const float* pre_Wq   = (const float*)d_in[1];
    const float* pre_Wk   = (const float*)d_in[2];
    const float* pre_Wv   = (const float*)d_in[3];
    const float* ln1_g    = (const float*)d_in[4];
    const float* ln1_b    = (const float*)d_in[5];
    const float* pre_W1   = (const float*)d_in[6];
    const float* pre_b1   = (const float*)d_in[7];
    const float* pre_W2   = (const float*)d_in[8];
    const float* pre_b2   = (const float*)d_in[9];
    const float* ln4p_g   = (const float*)d_in[10];
    const float* ln4p_b   = (const float*)d_in[11];
    const float* cross_Wq = (const float*)d_in[12];
    const float* cross_Wk = (const float*)d_in[13];
    const float* cross_Wv = (const float*)d_in[14];
    const float* ln2_g    = (const float*)d_in[15];
    const float* ln2_b    = (const float*)d_in[16];
    const float* post_Wq  = (const float*)d_in[17];
    const float* post_Wk  = (const float*)d_in[18];
    const float* post_Wv  = (const float*)d_in[19];
    const float* ln3_g    = (const float*)d_in[20];
    const float* ln3_b    = (const float*)d_in[21];
    const float* post_W1  = (const float*)d_in[22];
    const float* post_b1  = (const float*)d_in[23];
    const float* post_W2  = (const float*)d_in[24];
    const float* post_b2  = (const float*)d_in[25];
    const float* ln4_g    = (const float*)d_in[26];
    const float* ln4_b    = (const float*)d_in[27];
    float* out = (float*)d_out;

    __half *xh, *lnh, *xtph, *qkh, *avh, *scoresh, *wh;
    float* rsum;
    cudaGetSymbolAddress((void**)&xh, g_xh);
    cudaGetSymbolAddress((void**)&lnh, g_lnh);
    cudaGetSymbolAddress((void**)&xtph, g_xtph);
    cudaGetSymbolAddress((void**)&qkh, g_qkh);
    cudaGetSymbolAddress((void**)&avh, g_avh);
    cudaGetSymbolAddress((void**)&scoresh, g_scoresh);
    cudaGetSymbolAddress((void**)&rsum, g_rsum);
    cudaGetSymbolAddress((void**)&wh, g_wh);

    const long SZ_QKW = (long)SS * DD * QKN;
    const long SZ_VW  = (long)SS * DD * DD;
    const long SZ_W1  = (long)SS * DD * DD4;
    __half* qkPreH   = wh;
    __half* qkPostH  = qkPreH  + SZ_QKW;
    __half* qkCrossH = qkPostH + SZ_QKW;
    __half* WvPreH   = qkCrossH + (long)DD * QKN;
    __half* WvPostH  = WvPreH  + SZ_VW;
    __half* WvCrossH = WvPostH + SZ_VW;
    __half* W1PreH   = WvCrossH + (long)DD * DD;
    __half* W1PostH  = W1PreH  + SZ_W1;
    __half* W2PreH   = W1PostH + SZ_W1;
    __half* W2PostH  = W2PreH  + SZ_W1;

    const float scale = 1.0f / sqrtf((float)DD4);
    const long LD = (long)LL * DD;

    // ---------------- weight prep: pure streaming f2h / concat ----------
    concat_qk_kernel<<<cdiv((int)SZ_QKW, 256), 256>>>(pre_Wq, pre_Wk, qkPreH, SZ_QKW);
    concat_qk_kernel<<<cdiv((int)SZ_QKW, 256), 256>>>(post_Wq, post_Wk, qkPostH, SZ_QKW);
    concat_qk_kernel<<<cdiv((int)(DD * QKN), 256), 256>>>(cross_Wq, cross_Wk, qkCrossH, (long)DD * QKN);
    f2h_kernel<<<cdiv((int)(SZ_VW / 4), 256), 256>>>(pre_Wv,  WvPreH,  SZ_VW / 4);
    f2h_kernel<<<cdiv((int)(SZ_VW / 4), 256), 256>>>(post_Wv, WvPostH, SZ_VW / 4);
    f2h_kernel<<<cdiv((int)((long)DD * DD / 4), 256), 256>>>(cross_Wv, WvCrossH, (long)DD * DD / 4);
    f2h_kernel<<<cdiv((int)(SZ_W1 / 4), 256), 256>>>(pre_W1,  W1PreH,  SZ_W1 / 4);
    f2h_kernel<<<cdiv((int)(SZ_W1 / 4), 256), 256>>>(post_W1, W1PostH, SZ_W1 / 4);
    f2h_kernel<<<cdiv((int)(SZ_W1 / 4), 256), 256>>>(pre_W2,  W2PreH,  SZ_W1 / 4);
    f2h_kernel<<<cdiv((int)(SZ_W1 / 4), 256), 256>>>(post_W2, W2PostH, SZ_W1 / 4);
    f2h_kernel<<<cdiv((int)(SS * LD / 4), 256), 256>>>(x, xh, SS * LD / 4);

    // ================= pre_self_step attention =================
    launch_gemm<false, 0, 128>(xh, qkPreH, nullptr, qkh, LL, QKN, DD, DD, QKN, QKN, SS,
                               LD, (long)DD * QKN, 0, (long)LL * QKN);
    launch_gemm<true, 3, 256>(qkh, qkh + DD4, nullptr, scoresh, LL, LL, DD4, QKN, QKN, LL, SS,
                              (long)LL * QKN, (long)LL * QKN, 0, (long)LL * LL, scale);
    rowsum_kernel<<<SS * LL / 8, 256>>>(scoresh, rsum, LL, LL, (long)SS * LL);
    launch_gemm<false, 4, 256>(scoresh, xh, nullptr, avh, LL, DD, LL, LL, DD, DD, SS,
                               (long)LL * LL, LD, 0, LD, 0.0f, rsum, LL);
    launch_gemm<false, 0, 256>(avh, WvPreH, nullptr, scoresh, LL, DD, DD, DD, DD, DD, SS,
                               LD, (long)DD * DD, 0, LD);
    ln_kernel<<<SS * LL / 8, 256>>>(xh, scoresh, ln1_g, ln1_b, lnh, nullptr, LL,
                                    LL, 1, LL, 1, LL, 1, DD, (long)SS * LL);

    // ================= pre_mlp =================
    launch_gemm<false, 2, 192>(lnh, W1PreH, pre_b1, qkh, LL, DD4, DD, DD, DD4, DD4, SS,
                               LD, (long)DD * DD4, DD4, (long)LL * DD4);
    launch_gemm<false, 1, 256>(qkh, W2PreH, pre_b2, scoresh, LL, DD, DD4, DD4, DD, DD, SS,
                               (long)LL * DD4, (long)DD4 * DD, DD, LD);
    ln_kernel<<<SS * LL / 8, 256>>>(lnh, scoresh, ln4p_g, ln4p_b, xtph, nullptr, LL,
                                    LL, 1, LL, 1, 1, SP, DD, (long)SS * LL);
    zero_pad_kernel<<<cdiv(LL * (SP - SS) * DD, 256), 256>>>(xtph);

    // ================= cross_step attention (padded S -> SP) =================
    launch_gemm<false, 0, 128>(xtph, qkCrossH, nullptr, qkh, LL * SP, QKN, DD, DD, QKN, QKN, 1,
                               0, 0, 0, 0);
    launch_gemm<true, 3, 128>(qkh, qkh + DD4, nullptr, avh, SP, SP, DD4, QKN, QKN, SP, LL,
                              (long)SP * QKN, (long)SP * QKN, 0, (long)SP * SP, scale);
    rowsum_kernel<<<LL * SP / 8, 256>>>(avh, rsum, SS, SP, (long)LL * SP);
    launch_gemm<false, 4, 256>(avh, xtph, nullptr, scoresh, SS, DD, SP, SP, DD, DD, LL,
                               (long)SP * SP, (long)SP * DD, 0, (long)SS * DD, 0.0f, rsum, SP);
    launch_gemm<false, 0, 256>(scoresh, WvCrossH, nullptr, avh, LL * SS, DD, DD, DD, DD, DD, 1,
                               0, 0, 0, 0);
    ln_kernel<<<LL * SS / 8, 256>>>(xtph, avh, ln2_g, ln2_b, lnh, nullptr, SS,
                                    SP, 1, SS, 1, 1, LL, 0, (long)LL * SS);

    // ================= post_self_step attention =================
    launch_gemm<false, 0, 128>(lnh, qkPostH, nullptr, qkh, LL, QKN, DD, DD, QKN, QKN, SS,
                               LD, (long)DD * QKN, 0, (long)LL * QKN);
    launch_gemm<true, 3, 256>(qkh, qkh + DD4, nullptr, scoresh, LL, LL, DD4, QKN, QKN, LL, SS,
                              (long)LL * QKN, (long)LL * QKN, 0, (long)LL * LL, scale);
    rowsum_kernel<<<SS * LL / 8, 256>>>(scoresh, rsum, LL, LL, (long)SS * LL);
    launch_gemm<false, 4, 256>(scoresh, lnh, nullptr, avh, LL, DD, LL, LL, DD, DD, SS,
                               (long)LL * LL, LD, 0, LD, 0.0f, rsum, LL);
    launch_gemm<false, 0, 256>(avh, WvPostH, nullptr, scoresh, LL, DD, DD, DD, DD, DD, SS,
                               LD, (long)DD * DD, 0, LD);
    ln_kernel<<<SS * LL / 8, 256>>>(lnh, scoresh, ln3_g, ln3_b, xh, nullptr, LL,
                                    LL, 1, LL, 1, LL, 1, DD, (long)SS * LL);

    // ================= post_mlp =================
    launch_gemm<false, 2, 192>(xh, W1PostH, post_b1, qkh, LL, DD4, DD, DD, DD4, DD4, SS,
                               LD, (long)DD * DD4, DD4, (long)LL * DD4);
    launch_gemm<false, 1, 256>(qkh, W2PostH, post_b2, scoresh, LL, DD, DD4, DD4, DD, DD, SS,
                               (long)LL * DD4, (long)DD4 * DD, DD, LD);
    ln_kernel<<<SS * LL / 8, 256>>>(xh, scoresh, ln4_g, ln4_b, nullptr, out, LL,
                                    LL, 1, LL, 1, LL, 1, DD, (long)SS * LL);
}